// round 13
// baseline (speedup 1.0000x reference)
#include <cuda_runtime.h>
#include <cstdint>
#include <cstddef>

#define N_NODES 50000
#define SCAN_T 512
#define NSCAN_BLOCKS ((N_NODES + SCAN_T - 1) / SCAN_T)   // 98

// ---------------- scratch (device globals: no allocation allowed) ----------------
__device__ __align__(256) float g_P[N_NODES * 64];
__device__ __align__(256) float g_R[N_NODES * 64];
__device__ __align__(256) float g_H[N_NODES * 192];
__device__ __align__(256) float g_U[N_NODES * 64];
__device__ __align__(256) float g_V[N_NODES * 64];
__device__ __align__(256) float g_wU[N_NODES];
__device__ __align__(256) float g_wV[N_NODES];
__device__ __align__(256) float g_deginv[N_NODES];
__device__ __align__(256) int   g_cnt[N_NODES];
__device__ __align__(256) int   g_off[N_NODES];
__device__ __align__(256) int   g_cur[N_NODES];
__device__ __align__(256) int   g_bsum[128];
__device__ __align__(256) int   g_adj[800000];

// ---------------- CSR build (parallel 3-kernel scan, measured good) ----------------
__global__ void zero_int_kernel(int* __restrict__ p, int n) {
    int i = blockIdx.x * blockDim.x + threadIdx.x;
    if (i < n) p[i] = 0;
}

__global__ void count_deg_kernel(const int* __restrict__ dst, int* __restrict__ cnt, int E) {
    int e = blockIdx.x * blockDim.x + threadIdx.x;
    if (e < E) atomicAdd(&cnt[dst[e]], 1);
}

__global__ void scan1_kernel(const int* __restrict__ cnt, int* __restrict__ off,
                             int* __restrict__ bsum, int n) {
    __shared__ int sh[SCAN_T];
    int tid = threadIdx.x;
    int i = blockIdx.x * SCAN_T + tid;
    int v = (i < n) ? cnt[i] : 0;
    sh[tid] = v;
    __syncthreads();
#pragma unroll
    for (int d = 1; d < SCAN_T; d <<= 1) {
        int t = (tid >= d) ? sh[tid - d] : 0;
        __syncthreads();
        sh[tid] += t;
        __syncthreads();
    }
    if (i < n) off[i] = sh[tid] - v;
    if (tid == SCAN_T - 1) bsum[blockIdx.x] = sh[tid];
}

__global__ void scan2_kernel(int* __restrict__ bsum, int nb) {
    __shared__ int sh[128];
    int tid = threadIdx.x;
    int v = (tid < nb) ? bsum[tid] : 0;
    sh[tid] = v;
    __syncthreads();
#pragma unroll
    for (int d = 1; d < 128; d <<= 1) {
        int t = (tid >= d) ? sh[tid - d] : 0;
        __syncthreads();
        sh[tid] += t;
        __syncthreads();
    }
    if (tid < nb) bsum[tid] = sh[tid] - v;
}

__global__ void scan3_kernel(int* __restrict__ off, int* __restrict__ cur,
                             const int* __restrict__ cnt, const int* __restrict__ bsum,
                             float* __restrict__ deginv, int n) {
    int i = blockIdx.x * blockDim.x + threadIdx.x;
    if (i >= n) return;
    int o = off[i] + bsum[i / SCAN_T];
    off[i] = o;
    cur[i] = o;
    deginv[i] = 1.0f / fmaxf((float)cnt[i], 1.0f);
}

__global__ void fill_kernel(const int* __restrict__ src, const int* __restrict__ dst,
                            int* __restrict__ cur, int* __restrict__ adj, int E) {
    int e = blockIdx.x * blockDim.x + threadIdx.x;
    if (e >= E) return;
    int d = dst[e];
    int pos = atomicAdd(&cur[d], 1);
    adj[pos] = src[e];
}

// ---------------- tf32 helpers ----------------
__device__ __forceinline__ uint2 split_tf32(float x) {
    unsigned hi, lo;
    asm("cvt.rna.tf32.f32 %0, %1;" : "=r"(hi) : "f"(x));
    float r = x - __uint_as_float(hi);
    asm("cvt.rna.tf32.f32 %0, %1;" : "=r"(lo) : "f"(r));
    return make_uint2(hi, lo);
}

__device__ __forceinline__ void mma8(float* d, unsigned a0, unsigned a1,
                                     unsigned a2, unsigned a3,
                                     unsigned b0, unsigned b1) {
    asm volatile(
        "mma.sync.aligned.m16n8k8.row.col.f32.tf32.tf32.f32 "
        "{%0,%1,%2,%3}, {%4,%5,%6,%7}, {%8,%9}, {%0,%1,%2,%3};"
        : "+f"(d[0]), "+f"(d[1]), "+f"(d[2]), "+f"(d[3])
        : "r"(a0), "r"(a1), "r"(a2), "r"(a3), "r"(b0), "r"(b1));
}

// ---------------- tensor-core dual-output GEMM (2-term tf32 split) ----------------
// Optional biasT: added to the Ot (warpN==0) output columns in the epilogue.
#define TBK 16
#define SROW 18
#define ATILE (128 * SROW)

__device__ __forceinline__ void stash(uint2* base, int row, int kq, float4 v) {
    uint2* p = base + row * SROW + kq * 4;
    p[0] = split_tf32(v.x);
    p[1] = split_tf32(v.y);
    p[2] = split_tf32(v.z);
    p[3] = split_tf32(v.w);
}

__global__ __launch_bounds__(256, 2) void gemm_dual_tc(
    const float* __restrict__ A, int lda, int K,
    const float* __restrict__ Wt, const float* __restrict__ Wb, int wld,
    float* __restrict__ Ot, float* __restrict__ Ob,
    const float* __restrict__ biasT, int nNodes)
{
    extern __shared__ uint2 smem_u2[];
    uint2* Ash = smem_u2;
    uint2* Wsh = smem_u2 + 2 * ATILE;

    const int t = threadIdx.x;
    const int lane = t & 31, warp = t >> 5;
    const int grp = lane >> 2, tig = lane & 3;
    const int warpM = warp >> 1, warpN = warp & 1;
    const int m0 = blockIdx.x * 128;

    const int lm = t >> 2;
    const int lkq = t & 3;
    const int ar0 = min(m0 + lm, nNodes - 1);
    const int ar1 = min(m0 + lm + 64, nNodes - 1);
    const float* aptr0 = A + (size_t)ar0 * lda + lkq * 4;
    const float* aptr1 = A + (size_t)ar1 * lda + lkq * 4;
    const float* wptr0 = Wt + (size_t)lm * wld + lkq * 4;
    const float* wptr1 = Wb + (size_t)lm * wld + lkq * 4;

    float acc[2][8][4];
#pragma unroll
    for (int mt = 0; mt < 2; mt++)
#pragma unroll
        for (int nt = 0; nt < 8; nt++)
#pragma unroll
            for (int j = 0; j < 4; j++) acc[mt][nt][j] = 0.f;

    const int ntiles = K / TBK;

    float4 pa0 = *(const float4*)(aptr0);
    float4 pa1 = *(const float4*)(aptr1);
    float4 pw0 = *(const float4*)(wptr0);
    float4 pw1 = *(const float4*)(wptr1);
    stash(Ash, lm, lkq, pa0);
    stash(Ash, lm + 64, lkq, pa1);
    stash(Wsh, lm, lkq, pw0);
    stash(Wsh, lm + 64, lkq, pw1);
    __syncthreads();

    for (int tt = 0; tt < ntiles; tt++) {
        const int cur = tt & 1;
        const bool more = (tt + 1 < ntiles);
        if (more) {
            const int ko = (tt + 1) * TBK;
            pa0 = *(const float4*)(aptr0 + ko);
            pa1 = *(const float4*)(aptr1 + ko);
            pw0 = *(const float4*)(wptr0 + ko);
            pw1 = *(const float4*)(wptr1 + ko);
        }
        const uint2* Ab = Ash + cur * ATILE;
        const uint2* Wc = Wsh + cur * ATILE;
#pragma unroll
        for (int ks = 0; ks < 2; ks++) {
            const int kb = ks * 8;
            uint2 af[2][4];
#pragma unroll
            for (int mt = 0; mt < 2; mt++) {
                const uint2* ap = Ab + (warpM * 32 + mt * 16 + grp) * SROW + kb + tig;
                af[mt][0] = ap[0];
                af[mt][1] = ap[8 * SROW];
                af[mt][2] = ap[4];
                af[mt][3] = ap[8 * SROW + 4];
            }
#pragma unroll
            for (int nt = 0; nt < 8; nt++) {
                const uint2* wp = Wc + (warpN * 64 + nt * 8 + grp) * SROW + kb + tig;
                const uint2 b0 = wp[0];
                const uint2 b1 = wp[4];
#pragma unroll
                for (int mt = 0; mt < 2; mt++) {
                    // 2-term split: ah*bh + al*bh
                    mma8(acc[mt][nt], af[mt][0].x, af[mt][1].x, af[mt][2].x, af[mt][3].x, b0.x, b1.x);
                    mma8(acc[mt][nt], af[mt][0].y, af[mt][1].y, af[mt][2].y, af[mt][3].y, b0.x, b1.x);
                }
            }
        }
        if (more) {
            const int nxt = cur ^ 1;
            stash(Ash + nxt * ATILE, lm, lkq, pa0);
            stash(Ash + nxt * ATILE, lm + 64, lkq, pa1);
            stash(Wsh + nxt * ATILE, lm, lkq, pw0);
            stash(Wsh + nxt * ATILE, lm + 64, lkq, pw1);
        }
        __syncthreads();
    }

    // bias fold into Ot half
    if (biasT != nullptr && warpN == 0) {
#pragma unroll
        for (int nt = 0; nt < 8; nt++) {
            const int col = nt * 8 + tig * 2;
            float bb0 = __ldg(biasT + col);
            float bb1 = __ldg(biasT + col + 1);
#pragma unroll
            for (int mt = 0; mt < 2; mt++) {
                acc[mt][nt][0] += bb0; acc[mt][nt][1] += bb1;
                acc[mt][nt][2] += bb0; acc[mt][nt][3] += bb1;
            }
        }
    }

    float* O = warpN ? Ob : Ot;
#pragma unroll
    for (int mt = 0; mt < 2; mt++) {
#pragma unroll
        for (int nt = 0; nt < 8; nt++) {
            const int r0 = m0 + warpM * 32 + mt * 16 + grp;
            const int r1 = r0 + 8;
            const int col = nt * 8 + tig * 2;
            if (r0 < nNodes)
                *(float2*)(O + (size_t)r0 * 64 + col) = make_float2(acc[mt][nt][0], acc[mt][nt][1]);
            if (r1 < nNodes)
                *(float2*)(O + (size_t)r1 * 64 + col) = make_float2(acc[mt][nt][2], acc[mt][nt][3]);
        }
    }
}

#define GEMM_SMEM (4 * ATILE * (int)sizeof(uint2))   // 73728 bytes

// ---------------- CSR gather + combine ----------------
__global__ __launch_bounds__(256) void gather_combine(
    const float* __restrict__ P, const int* __restrict__ adj,
    const int* __restrict__ off, const int* __restrict__ cnt,
    const float* __restrict__ deginv, const float* __restrict__ R,
    const float* __restrict__ bl, float* __restrict__ H, int col, int n)
{
    int tid = blockIdx.x * blockDim.x + threadIdx.x;
    int nn = tid >> 4;
    int q  = tid & 15;
    if (nn >= n) return;
    const int beg = __ldg(off + nn);
    const int c   = __ldg(cnt + nn);
    const float4* Pq = (const float4*)P + q;

    float4 acc = make_float4(0.f, 0.f, 0.f, 0.f);
    int s0 = (c > 0) ? __ldg(adj + beg) : 0;
    for (int j = 0; j < c; j++) {
        int s1 = (j + 1 < c) ? __ldg(adj + beg + j + 1) : 0;
        float4 v = __ldg(Pq + (size_t)s0 * 16);
        acc.x += v.x; acc.y += v.y; acc.z += v.z; acc.w += v.w;
        s0 = s1;
    }
    const float di = __ldg(deginv + nn);
    const float4 r = *(const float4*)(R + (size_t)nn * 64 + q * 4);
    const float4 b = *(const float4*)(bl + q * 4);
    float4 h;
    h.x = fmaxf(fmaf(acc.x, di, b.x) + r.x, 0.f);
    h.y = fmaxf(fmaf(acc.y, di, b.y) + r.y, 0.f);
    h.z = fmaxf(fmaf(acc.z, di, b.z) + r.z, 0.f);
    h.w = fmaxf(fmaf(acc.w, di, b.w) + r.w, 0.f);
    *(float4*)(H + (size_t)nn * 192 + col + q * 4) = h;
}

// ---------------- per-node dot products: wU[n] = w . U'[n], wV[n] = w . V[n] ----------------
__global__ __launch_bounds__(256) void node_dots_kernel(
    const float* __restrict__ U, const float* __restrict__ V,
    const float* __restrict__ w64, float* __restrict__ wU, float* __restrict__ wV, int n)
{
    int tid = blockIdx.x * blockDim.x + threadIdx.x;
    int node = tid >> 2, q = tid & 3;
    if (node >= n) return;
    const float4* up = (const float4*)(U + (size_t)node * 64) + q * 4;
    const float4* vp = (const float4*)(V + (size_t)node * 64) + q * 4;
    const float4* wp = (const float4*)w64 + q * 4;
    float su = 0.f, sv = 0.f;
#pragma unroll
    for (int k = 0; k < 4; k++) {
        float4 u = __ldg(up + k), v = __ldg(vp + k), w = __ldg(wp + k);
        su += u.x * w.x + u.y * w.y + u.z * w.z + u.w * w.w;
        sv += v.x * w.x + v.y * w.y + v.z * w.z + v.w * w.w;
    }
    su += __shfl_xor_sync(0xffffffff, su, 1);
    su += __shfl_xor_sync(0xffffffff, su, 2);
    sv += __shfl_xor_sync(0xffffffff, sv, 1);
    sv += __shfl_xor_sync(0xffffffff, sv, 2);
    if (q == 0) { wU[node] = su; wV[node] = sv; }
}

// ---------------- edge head (relu-abs identity; U is bias-folded U') ----------------
// out = 0.5*(wU'[s] + wV[d] + sum_c w_c*|u'_c + v_c|) + bm2
__global__ __launch_bounds__(256) void edge_kernel(
    const float* __restrict__ U, const float* __restrict__ V,
    const float* __restrict__ wU, const float* __restrict__ wV,
    const int* __restrict__ src, const int* __restrict__ dst,
    const float* __restrict__ Wm2, const float* __restrict__ bm2,
    float* __restrict__ out, int E)
{
    __shared__ float wsh[64];
    int t = threadIdx.x;
    if (t < 64) wsh[t] = Wm2[t];
    __syncthreads();

    int e = blockIdx.x * blockDim.x + t;
    if (e >= E) return;
    int s = __ldg(src + e);
    int d = __ldg(dst + e);
    const float4* up = (const float4*)(U + (size_t)s * 64);
    const float4* vp = (const float4*)(V + (size_t)d * 64);
    float acc = 0.f;
#pragma unroll 4
    for (int j = 0; j < 16; j++) {
        float4 u = __ldg(up + j);
        float4 v = __ldg(vp + j);
        float4 w = *(const float4*)&wsh[j * 4];
        acc += fabsf(u.x + v.x) * w.x;
        acc += fabsf(u.y + v.y) * w.y;
        acc += fabsf(u.z + v.z) * w.z;
        acc += fabsf(u.w + v.w) * w.w;
    }
    out[e] = 0.5f * (__ldg(wU + s) + __ldg(wV + d) + acc) + __ldg(bm2);
}

// ---------------- host launcher ----------------
extern "C" void kernel_launch(void* const* d_in, const int* in_sizes, int n_in,
                              void* d_out, int out_size)
{
    const float* x   = (const float*)d_in[0];
    const int*   src = (const int*)d_in[1];
    const int*   dst = (const int*)d_in[2];
    const float* Wl0 = (const float*)d_in[3];
    const float* bl0 = (const float*)d_in[4];
    const float* Wr0 = (const float*)d_in[5];
    const float* Wl1 = (const float*)d_in[6];
    const float* bl1 = (const float*)d_in[7];
    const float* Wr1 = (const float*)d_in[8];
    const float* Wl2 = (const float*)d_in[9];
    const float* bl2 = (const float*)d_in[10];
    const float* Wr2 = (const float*)d_in[11];
    const float* Wm1 = (const float*)d_in[12];
    const float* bm1 = (const float*)d_in[13];
    const float* Wm2 = (const float*)d_in[14];
    const float* bm2 = (const float*)d_in[15];
    float* out = (float*)d_out;
    const int E = in_sizes[1];

    void* p;
    cudaGetSymbolAddress(&p, g_P);      float* P      = (float*)p;
    cudaGetSymbolAddress(&p, g_R);      float* R      = (float*)p;
    cudaGetSymbolAddress(&p, g_H);      float* H      = (float*)p;
    cudaGetSymbolAddress(&p, g_U);      float* U      = (float*)p;
    cudaGetSymbolAddress(&p, g_V);      float* V      = (float*)p;
    cudaGetSymbolAddress(&p, g_wU);     float* wU     = (float*)p;
    cudaGetSymbolAddress(&p, g_wV);     float* wV     = (float*)p;
    cudaGetSymbolAddress(&p, g_deginv); float* deginv = (float*)p;
    cudaGetSymbolAddress(&p, g_cnt);    int*   cnt    = (int*)p;
    cudaGetSymbolAddress(&p, g_off);    int*   off    = (int*)p;
    cudaGetSymbolAddress(&p, g_cur);    int*   cur    = (int*)p;
    cudaGetSymbolAddress(&p, g_bsum);   int*   bsum   = (int*)p;
    cudaGetSymbolAddress(&p, g_adj);    int*   adj    = (int*)p;

    cudaFuncSetAttribute(gemm_dual_tc, cudaFuncAttributeMaxDynamicSharedMemorySize, GEMM_SMEM);

    const int T = 256;
    const int gemm_blocks = (N_NODES + 127) / 128;
    const int gc_blocks   = (N_NODES * 16 + T - 1) / T;

    // ---- CSR build (parallel scan) ----
    zero_int_kernel<<<(N_NODES + T - 1) / T, T>>>(cnt, N_NODES);
    count_deg_kernel<<<(E + T - 1) / T, T>>>(dst, cnt, E);
    scan1_kernel<<<NSCAN_BLOCKS, SCAN_T>>>(cnt, off, bsum, N_NODES);
    scan2_kernel<<<1, 128>>>(bsum, NSCAN_BLOCKS);
    scan3_kernel<<<(N_NODES + T - 1) / T, T>>>(off, cur, cnt, bsum, deginv, N_NODES);
    fill_kernel<<<(E + T - 1) / T, T>>>(src, dst, cur, adj, E);

    // ---- SAGE layer 0 ----
    gemm_dual_tc<<<gemm_blocks, 256, GEMM_SMEM>>>(x, 128, 128, Wl0, Wr0, 128, P, R, nullptr, N_NODES);
    gather_combine<<<gc_blocks, T>>>(P, adj, off, cnt, deginv, R, bl0, H, 0, N_NODES);

    // ---- SAGE layer 1 ----
    gemm_dual_tc<<<gemm_blocks, 256, GEMM_SMEM>>>(H, 192, 64, Wl1, Wr1, 64, P, R, nullptr, N_NODES);
    gather_combine<<<gc_blocks, T>>>(P, adj, off, cnt, deginv, R, bl1, H, 64, N_NODES);

    // ---- SAGE layer 2 ----
    gemm_dual_tc<<<gemm_blocks, 256, GEMM_SMEM>>>(H + 64, 192, 64, Wl2, Wr2, 64, P, R, nullptr, N_NODES);
    gather_combine<<<gc_blocks, T>>>(P, adj, off, cnt, deginv, R, bl2, H, 128, N_NODES);

    // ---- edge MLP decomposition: U' = H @ W1a^T + bm1 (bias folded), V = H @ W1b^T ----
    gemm_dual_tc<<<gemm_blocks, 256, GEMM_SMEM>>>(H, 192, 192, Wm1, Wm1 + 192, 384, U, V, bm1, N_NODES);

    // ---- per-node dots for the relu-abs identity ----
    node_dots_kernel<<<(N_NODES * 4 + T - 1) / T, T>>>(U, V, Wm2, wU, wV, N_NODES);

    // ---- per-edge head ----
    edge_kernel<<<(E + T - 1) / T, T>>>(U, V, wU, wV, src, dst, Wm2, bm2, out, E);
}

// round 14
// speedup vs baseline: 1.2304x; 1.2304x over previous
#include <cuda_runtime.h>
#include <cstdint>
#include <cstddef>

#define N_NODES 50000
#define SCAN_T 512
#define NSCAN_BLOCKS ((N_NODES + SCAN_T - 1) / SCAN_T)   // 98

// ---------------- scratch (device globals: no allocation allowed) ----------------
__device__ __align__(256) float g_P[N_NODES * 64];
__device__ __align__(256) float g_R[N_NODES * 64];
__device__ __align__(256) float g_H[N_NODES * 192];
__device__ __align__(256) float g_U[N_NODES * 64];
__device__ __align__(256) float g_V[N_NODES * 64];
__device__ __align__(256) float g_deginv[N_NODES];
__device__ __align__(256) int   g_cnt[N_NODES];
__device__ __align__(256) int   g_off[N_NODES];
__device__ __align__(256) int   g_cur[N_NODES];
__device__ __align__(256) int   g_bsum[128];
__device__ __align__(256) int   g_adj[800000];

// ---------------- CSR build (parallel 3-kernel scan, measured good) ----------------
__global__ void zero_int_kernel(int* __restrict__ p, int n) {
    int i = blockIdx.x * blockDim.x + threadIdx.x;
    if (i < n) p[i] = 0;
}

__global__ void count_deg_kernel(const int* __restrict__ dst, int* __restrict__ cnt, int E) {
    int e = blockIdx.x * blockDim.x + threadIdx.x;
    if (e < E) atomicAdd(&cnt[dst[e]], 1);
}

__global__ void scan1_kernel(const int* __restrict__ cnt, int* __restrict__ off,
                             int* __restrict__ bsum, int n) {
    __shared__ int sh[SCAN_T];
    int tid = threadIdx.x;
    int i = blockIdx.x * SCAN_T + tid;
    int v = (i < n) ? cnt[i] : 0;
    sh[tid] = v;
    __syncthreads();
#pragma unroll
    for (int d = 1; d < SCAN_T; d <<= 1) {
        int t = (tid >= d) ? sh[tid - d] : 0;
        __syncthreads();
        sh[tid] += t;
        __syncthreads();
    }
    if (i < n) off[i] = sh[tid] - v;
    if (tid == SCAN_T - 1) bsum[blockIdx.x] = sh[tid];
}

__global__ void scan2_kernel(int* __restrict__ bsum, int nb) {
    __shared__ int sh[128];
    int tid = threadIdx.x;
    int v = (tid < nb) ? bsum[tid] : 0;
    sh[tid] = v;
    __syncthreads();
#pragma unroll
    for (int d = 1; d < 128; d <<= 1) {
        int t = (tid >= d) ? sh[tid - d] : 0;
        __syncthreads();
        sh[tid] += t;
        __syncthreads();
    }
    if (tid < nb) bsum[tid] = sh[tid] - v;
}

__global__ void scan3_kernel(int* __restrict__ off, int* __restrict__ cur,
                             const int* __restrict__ cnt, const int* __restrict__ bsum,
                             float* __restrict__ deginv, int n) {
    int i = blockIdx.x * blockDim.x + threadIdx.x;
    if (i >= n) return;
    int o = off[i] + bsum[i / SCAN_T];
    off[i] = o;
    cur[i] = o;
    deginv[i] = 1.0f / fmaxf((float)cnt[i], 1.0f);
}

__global__ void fill_kernel(const int* __restrict__ src, const int* __restrict__ dst,
                            int* __restrict__ cur, int* __restrict__ adj, int E) {
    int e = blockIdx.x * blockDim.x + threadIdx.x;
    if (e >= E) return;
    int d = dst[e];
    int pos = atomicAdd(&cur[d], 1);
    adj[pos] = src[e];
}

// ---------------- tf32 helpers ----------------
__device__ __forceinline__ uint2 split_tf32(float x) {
    unsigned hi, lo;
    asm("cvt.rna.tf32.f32 %0, %1;" : "=r"(hi) : "f"(x));
    float r = x - __uint_as_float(hi);
    asm("cvt.rna.tf32.f32 %0, %1;" : "=r"(lo) : "f"(r));
    return make_uint2(hi, lo);
}

__device__ __forceinline__ void mma8(float* d, unsigned a0, unsigned a1,
                                     unsigned a2, unsigned a3,
                                     unsigned b0, unsigned b1) {
    asm volatile(
        "mma.sync.aligned.m16n8k8.row.col.f32.tf32.tf32.f32 "
        "{%0,%1,%2,%3}, {%4,%5,%6,%7}, {%8,%9}, {%0,%1,%2,%3};"
        : "+f"(d[0]), "+f"(d[1]), "+f"(d[2]), "+f"(d[3])
        : "r"(a0), "r"(a1), "r"(a2), "r"(a3), "r"(b0), "r"(b1));
}

// ---------------- tensor-core dual-output GEMM (2-term tf32 split) ----------------
#define TBK 16
#define SROW 18
#define ATILE (128 * SROW)

__device__ __forceinline__ void stash(uint2* base, int row, int kq, float4 v) {
    uint2* p = base + row * SROW + kq * 4;
    p[0] = split_tf32(v.x);
    p[1] = split_tf32(v.y);
    p[2] = split_tf32(v.z);
    p[3] = split_tf32(v.w);
}

__global__ __launch_bounds__(256, 2) void gemm_dual_tc(
    const float* __restrict__ A, int lda, int K,
    const float* __restrict__ Wt, const float* __restrict__ Wb, int wld,
    float* __restrict__ Ot, float* __restrict__ Ob,
    const float* __restrict__ biasT, int nNodes)
{
    extern __shared__ uint2 smem_u2[];
    uint2* Ash = smem_u2;
    uint2* Wsh = smem_u2 + 2 * ATILE;

    const int t = threadIdx.x;
    const int lane = t & 31, warp = t >> 5;
    const int grp = lane >> 2, tig = lane & 3;
    const int warpM = warp >> 1, warpN = warp & 1;
    const int m0 = blockIdx.x * 128;

    const int lm = t >> 2;
    const int lkq = t & 3;
    const int ar0 = min(m0 + lm, nNodes - 1);
    const int ar1 = min(m0 + lm + 64, nNodes - 1);
    const float* aptr0 = A + (size_t)ar0 * lda + lkq * 4;
    const float* aptr1 = A + (size_t)ar1 * lda + lkq * 4;
    const float* wptr0 = Wt + (size_t)lm * wld + lkq * 4;
    const float* wptr1 = Wb + (size_t)lm * wld + lkq * 4;

    float acc[2][8][4];
#pragma unroll
    for (int mt = 0; mt < 2; mt++)
#pragma unroll
        for (int nt = 0; nt < 8; nt++)
#pragma unroll
            for (int j = 0; j < 4; j++) acc[mt][nt][j] = 0.f;

    const int ntiles = K / TBK;

    float4 pa0 = *(const float4*)(aptr0);
    float4 pa1 = *(const float4*)(aptr1);
    float4 pw0 = *(const float4*)(wptr0);
    float4 pw1 = *(const float4*)(wptr1);
    stash(Ash, lm, lkq, pa0);
    stash(Ash, lm + 64, lkq, pa1);
    stash(Wsh, lm, lkq, pw0);
    stash(Wsh, lm + 64, lkq, pw1);
    __syncthreads();

    for (int tt = 0; tt < ntiles; tt++) {
        const int cur = tt & 1;
        const bool more = (tt + 1 < ntiles);
        if (more) {
            const int ko = (tt + 1) * TBK;
            pa0 = *(const float4*)(aptr0 + ko);
            pa1 = *(const float4*)(aptr1 + ko);
            pw0 = *(const float4*)(wptr0 + ko);
            pw1 = *(const float4*)(wptr1 + ko);
        }
        const uint2* Ab = Ash + cur * ATILE;
        const uint2* Wc = Wsh + cur * ATILE;
#pragma unroll
        for (int ks = 0; ks < 2; ks++) {
            const int kb = ks * 8;
            uint2 af[2][4];
#pragma unroll
            for (int mt = 0; mt < 2; mt++) {
                const uint2* ap = Ab + (warpM * 32 + mt * 16 + grp) * SROW + kb + tig;
                af[mt][0] = ap[0];
                af[mt][1] = ap[8 * SROW];
                af[mt][2] = ap[4];
                af[mt][3] = ap[8 * SROW + 4];
            }
#pragma unroll
            for (int nt = 0; nt < 8; nt++) {
                const uint2* wp = Wc + (warpN * 64 + nt * 8 + grp) * SROW + kb + tig;
                const uint2 b0 = wp[0];
                const uint2 b1 = wp[4];
#pragma unroll
                for (int mt = 0; mt < 2; mt++) {
                    // 2-term split: ah*bh + al*bh
                    mma8(acc[mt][nt], af[mt][0].x, af[mt][1].x, af[mt][2].x, af[mt][3].x, b0.x, b1.x);
                    mma8(acc[mt][nt], af[mt][0].y, af[mt][1].y, af[mt][2].y, af[mt][3].y, b0.x, b1.x);
                }
            }
        }
        if (more) {
            const int nxt = cur ^ 1;
            stash(Ash + nxt * ATILE, lm, lkq, pa0);
            stash(Ash + nxt * ATILE, lm + 64, lkq, pa1);
            stash(Wsh + nxt * ATILE, lm, lkq, pw0);
            stash(Wsh + nxt * ATILE, lm + 64, lkq, pw1);
        }
        __syncthreads();
    }

    // bias fold into Ot half
    if (biasT != nullptr && warpN == 0) {
#pragma unroll
        for (int nt = 0; nt < 8; nt++) {
            const int col = nt * 8 + tig * 2;
            float bb0 = __ldg(biasT + col);
            float bb1 = __ldg(biasT + col + 1);
#pragma unroll
            for (int mt = 0; mt < 2; mt++) {
                acc[mt][nt][0] += bb0; acc[mt][nt][1] += bb1;
                acc[mt][nt][2] += bb0; acc[mt][nt][3] += bb1;
            }
        }
    }

    float* O = warpN ? Ob : Ot;
#pragma unroll
    for (int mt = 0; mt < 2; mt++) {
#pragma unroll
        for (int nt = 0; nt < 8; nt++) {
            const int r0 = m0 + warpM * 32 + mt * 16 + grp;
            const int r1 = r0 + 8;
            const int col = nt * 8 + tig * 2;
            if (r0 < nNodes)
                *(float2*)(O + (size_t)r0 * 64 + col) = make_float2(acc[mt][nt][0], acc[mt][nt][1]);
            if (r1 < nNodes)
                *(float2*)(O + (size_t)r1 * 64 + col) = make_float2(acc[mt][nt][2], acc[mt][nt][3]);
        }
    }
}

#define GEMM_SMEM (4 * ATILE * (int)sizeof(uint2))   // 73728 bytes

// ---------------- CSR gather + combine ----------------
__global__ __launch_bounds__(256) void gather_combine(
    const float* __restrict__ P, const int* __restrict__ adj,
    const int* __restrict__ off, const int* __restrict__ cnt,
    const float* __restrict__ deginv, const float* __restrict__ R,
    const float* __restrict__ bl, float* __restrict__ H, int col, int n)
{
    int tid = blockIdx.x * blockDim.x + threadIdx.x;
    int nn = tid >> 4;
    int q  = tid & 15;
    if (nn >= n) return;
    const int beg = __ldg(off + nn);
    const int c   = __ldg(cnt + nn);
    const float4* Pq = (const float4*)P + q;

    float4 acc = make_float4(0.f, 0.f, 0.f, 0.f);
    int s0 = (c > 0) ? __ldg(adj + beg) : 0;
    for (int j = 0; j < c; j++) {
        int s1 = (j + 1 < c) ? __ldg(adj + beg + j + 1) : 0;
        float4 v = __ldg(Pq + (size_t)s0 * 16);
        acc.x += v.x; acc.y += v.y; acc.z += v.z; acc.w += v.w;
        s0 = s1;
    }
    const float di = __ldg(deginv + nn);
    const float4 r = *(const float4*)(R + (size_t)nn * 64 + q * 4);
    const float4 b = *(const float4*)(bl + q * 4);
    float4 h;
    h.x = fmaxf(fmaf(acc.x, di, b.x) + r.x, 0.f);
    h.y = fmaxf(fmaf(acc.y, di, b.y) + r.y, 0.f);
    h.z = fmaxf(fmaf(acc.z, di, b.z) + r.z, 0.f);
    h.w = fmaxf(fmaf(acc.w, di, b.w) + r.w, 0.f);
    *(float4*)(H + (size_t)nn * 192 + col + q * 4) = h;
}

// ---------------- edge head: 8 threads per edge (coalesced row reads) ----------------
// U carries bias-folded U' = H@W1a^T + bm1. out[e] = sum_c relu(u'_c + v_c)*w_c + bm2
__global__ __launch_bounds__(256) void edge_kernel8(
    const float* __restrict__ U, const float* __restrict__ V,
    const int* __restrict__ src, const int* __restrict__ dst,
    const float* __restrict__ Wm2, const float* __restrict__ bm2,
    float* __restrict__ out, int E)
{
    __shared__ float wsh[64];
    int t = threadIdx.x;
    if (t < 64) wsh[t] = Wm2[t];
    __syncthreads();

    int gid = blockIdx.x * blockDim.x + t;
    int e = gid >> 3;
    int q = gid & 7;
    if (e >= E) return;
    int s = __ldg(src + e);
    int d = __ldg(dst + e);
    const float4* up = (const float4*)(U + (size_t)s * 64) + q * 2;
    const float4* vp = (const float4*)(V + (size_t)d * 64) + q * 2;
    float acc = 0.f;
#pragma unroll
    for (int j = 0; j < 2; j++) {
        float4 u = __ldg(up + j);
        float4 v = __ldg(vp + j);
        const float4 w = *(const float4*)&wsh[q * 8 + j * 4];
        acc += fmaxf(u.x + v.x, 0.f) * w.x;
        acc += fmaxf(u.y + v.y, 0.f) * w.y;
        acc += fmaxf(u.z + v.z, 0.f) * w.z;
        acc += fmaxf(u.w + v.w, 0.f) * w.w;
    }
    acc += __shfl_xor_sync(0xffffffff, acc, 1);
    acc += __shfl_xor_sync(0xffffffff, acc, 2);
    acc += __shfl_xor_sync(0xffffffff, acc, 4);
    if (q == 0) out[e] = acc + __ldg(bm2);
}

// ---------------- host launcher ----------------
extern "C" void kernel_launch(void* const* d_in, const int* in_sizes, int n_in,
                              void* d_out, int out_size)
{
    const float* x   = (const float*)d_in[0];
    const int*   src = (const int*)d_in[1];
    const int*   dst = (const int*)d_in[2];
    const float* Wl0 = (const float*)d_in[3];
    const float* bl0 = (const float*)d_in[4];
    const float* Wr0 = (const float*)d_in[5];
    const float* Wl1 = (const float*)d_in[6];
    const float* bl1 = (const float*)d_in[7];
    const float* Wr1 = (const float*)d_in[8];
    const float* Wl2 = (const float*)d_in[9];
    const float* bl2 = (const float*)d_in[10];
    const float* Wr2 = (const float*)d_in[11];
    const float* Wm1 = (const float*)d_in[12];
    const float* bm1 = (const float*)d_in[13];
    const float* Wm2 = (const float*)d_in[14];
    const float* bm2 = (const float*)d_in[15];
    float* out = (float*)d_out;
    const int E = in_sizes[1];

    void* p;
    cudaGetSymbolAddress(&p, g_P);      float* P      = (float*)p;
    cudaGetSymbolAddress(&p, g_R);      float* R      = (float*)p;
    cudaGetSymbolAddress(&p, g_H);      float* H      = (float*)p;
    cudaGetSymbolAddress(&p, g_U);      float* U      = (float*)p;
    cudaGetSymbolAddress(&p, g_V);      float* V      = (float*)p;
    cudaGetSymbolAddress(&p, g_deginv); float* deginv = (float*)p;
    cudaGetSymbolAddress(&p, g_cnt);    int*   cnt    = (int*)p;
    cudaGetSymbolAddress(&p, g_off);    int*   off    = (int*)p;
    cudaGetSymbolAddress(&p, g_cur);    int*   cur    = (int*)p;
    cudaGetSymbolAddress(&p, g_bsum);   int*   bsum   = (int*)p;
    cudaGetSymbolAddress(&p, g_adj);    int*   adj    = (int*)p;

    cudaFuncSetAttribute(gemm_dual_tc, cudaFuncAttributeMaxDynamicSharedMemorySize, GEMM_SMEM);

    const int T = 256;
    const int gemm_blocks = (N_NODES + 127) / 128;
    const int gc_blocks   = (N_NODES * 16 + T - 1) / T;

    // ---- CSR build (parallel scan) ----
    zero_int_kernel<<<(N_NODES + T - 1) / T, T>>>(cnt, N_NODES);
    count_deg_kernel<<<(E + T - 1) / T, T>>>(dst, cnt, E);
    scan1_kernel<<<NSCAN_BLOCKS, SCAN_T>>>(cnt, off, bsum, N_NODES);
    scan2_kernel<<<1, 128>>>(bsum, NSCAN_BLOCKS);
    scan3_kernel<<<(N_NODES + T - 1) / T, T>>>(off, cur, cnt, bsum, deginv, N_NODES);
    fill_kernel<<<(E + T - 1) / T, T>>>(src, dst, cur, adj, E);

    // ---- SAGE layer 0 ----
    gemm_dual_tc<<<gemm_blocks, 256, GEMM_SMEM>>>(x, 128, 128, Wl0, Wr0, 128, P, R, nullptr, N_NODES);
    gather_combine<<<gc_blocks, T>>>(P, adj, off, cnt, deginv, R, bl0, H, 0, N_NODES);

    // ---- SAGE layer 1 ----
    gemm_dual_tc<<<gemm_blocks, 256, GEMM_SMEM>>>(H, 192, 64, Wl1, Wr1, 64, P, R, nullptr, N_NODES);
    gather_combine<<<gc_blocks, T>>>(P, adj, off, cnt, deginv, R, bl1, H, 64, N_NODES);

    // ---- SAGE layer 2 ----
    gemm_dual_tc<<<gemm_blocks, 256, GEMM_SMEM>>>(H + 64, 192, 64, Wl2, Wr2, 64, P, R, nullptr, N_NODES);
    gather_combine<<<gc_blocks, T>>>(P, adj, off, cnt, deginv, R, bl2, H, 128, N_NODES);

    // ---- edge MLP decomposition: U' = H @ W1a^T + bm1 (bias folded), V = H @ W1b^T ----
    gemm_dual_tc<<<gemm_blocks, 256, GEMM_SMEM>>>(H, 192, 192, Wm1, Wm1 + 192, 384, U, V, bm1, N_NODES);

    // ---- per-edge head: 8 threads/edge ----
    edge_kernel8<<<((size_t)E * 8 + T - 1) / T, T>>>(U, V, src, dst, Wm2, bm2, out, E);
}